// round 13
// baseline (speedup 1.0000x reference)
#include <cuda_runtime.h>
#include <math.h>
#include <stdint.h>

#define BB 8
#define TT 2048
#define DD 1024
#define FF 4096
#define EE 8

#define BM 128
#define BN 256
#define BKT 32
#define NTH 512
#define LDAU 32          // A smem row stride (u32): 128B rows, chunk-XOR swizzle
#define LDBU 264         // B smem row stride (u32) = 66 16B chunks

#define ASTG (BM * LDAU)     // 4096 u32 = 16KB
#define BSTG (BKT * LDBU)    // 8448 u32 = 33792B
#define STGU (ASTG + BSTG)   // u32 per stage
#define SMEM_BYTES (3 * STGU * 4)   // 150528 B

// ---------------- device scratch (no allocation allowed) -------------------
__device__ float g_pp[8 * BB * DD];               // pool partials (8 T-chunks)
__device__ int   g_eidx[BB * 2];
__device__ float g_ew[BB * 2];
__device__ float g_xr[(size_t)BB * TT * DD];      // 64MB: tf32 x, k-perm in 8-groups
__device__ float g_w1r[(size_t)EE * DD * FF];     // 128MB: tf32 W1, col-perm in 32-groups
__device__ float g_w2r[(size_t)EE * FF * DD];     // 128MB: tf32 W2, col-perm in 32-groups
__device__ float g_h[(size_t)BB * 2 * TT * FF];   // 512MB: tf32 h, k-perm in 8-groups

// ---------------- helpers ---------------------------------------------------
static __device__ __forceinline__ uint32_t smem_u32(const void* p) {
    uint32_t a;
    asm("{ .reg .u64 t; cvta.to.shared.u64 t, %1; cvt.u32.u64 %0, t; }" : "=r"(a) : "l"(p));
    return a;
}
static __device__ __forceinline__ uint32_t f2tf(float f) {
    uint32_t r;
    asm("cvt.rna.tf32.f32 %0, %1;" : "=r"(r) : "f"(f));
    return r;
}
static __device__ __forceinline__ float rtf(float f) { return __uint_as_float(f2tf(f)); }
static __device__ __forceinline__ void mma8(float* c, const uint32_t* a, const uint32_t* b) {
    asm volatile(
        "mma.sync.aligned.m16n8k8.row.col.f32.tf32.tf32.f32 "
        "{%0,%1,%2,%3}, {%4,%5,%6,%7}, {%8,%9}, {%0,%1,%2,%3};"
        : "+f"(c[0]), "+f"(c[1]), "+f"(c[2]), "+f"(c[3])
        : "r"(a[0]), "r"(a[1]), "r"(a[2]), "r"(a[3]), "r"(b[0]), "r"(b[1]));
}
static __device__ __forceinline__ void cpa16(uint32_t dst, const float* src) {
    asm volatile("cp.async.cg.shared.global [%0], [%1], 16;" :: "r"(dst), "l"(src));
}
static __device__ __forceinline__ void cpa_commit() {
    asm volatile("cp.async.commit_group;" ::: "memory");
}
static __device__ __forceinline__ void cpa_wait0() {
    asm volatile("cp.async.wait_group 0;" ::: "memory");
}
static __device__ __forceinline__ void cpa_wait1() {
    asm volatile("cp.async.wait_group 1;" ::: "memory");
}

// Issue one full stage (A tile + B tile) as one cp.async commit group.
// A: 128 rows x 32 k (k pre-permuted in gmem), chunks swizzled c^((r&3)<<1).
// B: 32 k x 256 n (pre-permuted in gmem), rows padded to 66 chunks.
static __device__ __forceinline__ void issue_stage(
    uint32_t base, const float* __restrict__ A, int lda,
    const float* __restrict__ B, int ldb, int tid)
{
#pragma unroll
    for (int it = 0; it < 2; it++) {
        int r = (tid >> 3) + it * 64;
        int c = tid & 7;
        cpa16(base + (uint32_t)(r * LDAU + ((c ^ ((r & 3) << 1)) << 2)) * 4u,
              A + (size_t)r * lda + c * 4);
    }
#pragma unroll
    for (int it = 0; it < 4; it++) {
        int idx = it * NTH + tid;
        int k = idx >> 6, c = idx & 63;
        cpa16(base + (uint32_t)ASTG * 4u + (uint32_t)(k * 66 + c) * 16u,
              B + (size_t)k * ldb + c * 4);
    }
    cpa_commit();
}

// Compute 32-k block. Warp grid 4m x 4n: warp tile 32(M) x 64(N).
// A frags: 2x LDS.64 (pair-perm layout puts k={tig,tig+4} adjacent).
// B frags: LDS.128 via n-permuted layout.
static __device__ __forceinline__ void compute32(const uint32_t* __restrict__ as,
                                                 const uint32_t* __restrict__ bs,
                                                 float acc[2][8][4],
                                                 int wm, int wn, int g, int tig) {
    int akey = (g & 3) << 1;                 // row swizzle key (rows g, g+8 share it)
    int aoff_in = 2 * (tig & 1);             // within-chunk u32 offset
    int ahalf = tig >> 1;                    // chunk select within k8 block
#pragma unroll
    for (int ks = 0; ks < 4; ks++) {
        int ck = 2 * ks + ahalf;
        int coff = ((ck ^ akey) << 2) + aoff_in;
        uint32_t a[2][4];
#pragma unroll
        for (int mi = 0; mi < 2; mi++) {
            int r0 = (wm * 32 + mi * 16 + g) * LDAU;
            uint2 p0 = *(const uint2*)&as[r0 + coff];
            uint2 p1 = *(const uint2*)&as[r0 + 8 * LDAU + coff];
            a[mi][0] = p0.x; a[mi][2] = p0.y;   // k = tig, tig+4 (row g)
            a[mi][1] = p1.x; a[mi][3] = p1.y;   // k = tig, tig+4 (row g+8)
        }
#pragma unroll
        for (int nj = 0; nj < 2; nj++) {
            int nb = wn * 64 + nj * 32 + g * 4;
            uint4 q0 = *(const uint4*)&bs[(ks * 8 + tig) * LDBU + nb];
            uint4 q1 = *(const uint4*)&bs[(ks * 8 + tig + 4) * LDBU + nb];
            uint32_t b0[4] = { q0.x, q0.y, q0.z, q0.w };
            uint32_t b1[4] = { q1.x, q1.y, q1.z, q1.w };
#pragma unroll
            for (int ni = 0; ni < 4; ni++) {
                uint32_t bb[2] = { b0[ni], b1[ni] };
#pragma unroll
                for (int mi = 0; mi < 2; mi++) mma8(acc[mi][nj * 4 + ni], a[mi], bb);
            }
        }
    }
}

// Mainloop: acc(128x256) += [A0;A1] @ [B0;B1]. 3-stage cp.async for A+B.
static __device__ __forceinline__ void gemm_core(
    const float* __restrict__ A0, const float* __restrict__ A1, int lda,
    const float* __restrict__ B0, const float* __restrict__ B1, int ldb,
    int nst, int half, uint32_t* smu, float acc[2][8][4])
{
    int tid = threadIdx.x;
    int wid = tid >> 5, lane = tid & 31;
    int wm = wid & 3, wn = wid >> 2;
    int g = lane >> 2, tig = lane & 3;

    uint32_t sb[3] = { smem_u32(smu), smem_u32(smu + STGU), smem_u32(smu + 2 * STGU) };

    // prologue: stages 0,1 in flight
#pragma unroll
    for (int t = 0; t < 2; t++) {
        int sel = (t >= half);
        int k0 = (t - (sel ? half : 0)) * BKT;
        issue_stage(sb[t], (sel ? A1 : A0) + k0, lda,
                    (sel ? B1 : B0) + (size_t)k0 * ldb, ldb, tid);
    }
    cpa_wait1();          // stage 0 complete
    __syncthreads();

    for (int s = 0; s < nst; s++) {
        int buf = s - (s / 3) * 3;      // s % 3
        if (s + 2 < nst) {
            int t = s + 2;
            int sel = (t >= half);
            int k0 = (t - (sel ? half : 0)) * BKT;
            int nb = buf + 2; if (nb >= 3) nb -= 3;
            issue_stage(sb[nb], (sel ? A1 : A0) + k0, lda,
                        (sel ? B1 : B0) + (size_t)k0 * ldb, ldb, tid);
        }
        const uint32_t* as = smu + buf * STGU;
        compute32(as, as + ASTG, acc, wm, wn, g, tig);
        if (s + 1 < nst) {
            if (s + 2 < nst) cpa_wait1(); else cpa_wait0();
            __syncthreads();
        }
    }
}

// ---------------- Kernel 0a: x -> tf32, k-perm within 8-groups --------------
// positions 0..7 hold logical k = 0,4,1,5,2,6,3,7
__global__ void prep_x(const float* __restrict__ x) {
    size_t gidx = (size_t)blockIdx.x * blockDim.x + threadIdx.x;
    const float4* s = (const float4*)x + gidx * 2;
    float4 v0 = s[0], v1 = s[1];
    float4 o0 = make_float4(rtf(v0.x), rtf(v1.x), rtf(v0.y), rtf(v1.y));
    float4 o1 = make_float4(rtf(v0.z), rtf(v1.z), rtf(v0.w), rtf(v1.w));
    float4* d = (float4*)g_xr + gidx * 2;
    d[0] = o0; d[1] = o1;
}
// ---------------- Kernel 0b: weights -> tf32 + col-perm in 32-groups --------
// out position 4*(n&7)+(n>>3) within each 32-group (matches smem B layout).
__global__ void prep_w(const float* __restrict__ w, float* __restrict__ dst) {
    size_t gidx = (size_t)blockIdx.x * blockDim.x + threadIdx.x;
    const float4* s = (const float4*)w + gidx * 8;
    float v[32];
#pragma unroll
    for (int i = 0; i < 8; i++) {
        float4 t = s[i];
        v[4 * i] = t.x; v[4 * i + 1] = t.y; v[4 * i + 2] = t.z; v[4 * i + 3] = t.w;
    }
    float4* d = (float4*)dst + gidx * 8;
#pragma unroll
    for (int m = 0; m < 8; m++)
        d[m] = make_float4(rtf(v[m]), rtf(v[m + 8]), rtf(v[m + 16]), rtf(v[m + 24]));
}

// ---------------- Kernel 1: mean pool partials (8 T-chunks) -----------------
__global__ void pool_kernel(const float* __restrict__ x) {
    int b = blockIdx.x;
    int d = blockIdx.y * blockDim.x + threadIdx.x;
    int c = blockIdx.z;
    const float* xp = x + (size_t)b * TT * DD + (size_t)(c * (TT / 8)) * DD + d;
    float s = 0.0f;
#pragma unroll 8
    for (int t = 0; t < TT / 8; t++) s += xp[(size_t)t * DD];
    g_pp[(c * BB + b) * DD + d] = s;
}

// ---------------- Kernel 2: routing (reduces pool partials) -----------------
__global__ void route_kernel(const float* __restrict__ Wr) {
    int w = threadIdx.x >> 5;
    int lane = threadIdx.x & 31;
    if (w >= BB) return;
    float sums[EE];
#pragma unroll
    for (int e = 0; e < EE; e++) sums[e] = 0.0f;
    for (int d = lane; d < DD; d += 32) {
        float p = 0.0f;
#pragma unroll
        for (int c = 0; c < 8; c++) p += g_pp[(c * BB + w) * DD + d];
        p *= (1.0f / (float)TT);
        const float* wr = Wr + d * EE;
#pragma unroll
        for (int e = 0; e < EE; e++) sums[e] += p * wr[e];
    }
#pragma unroll
    for (int e = 0; e < EE; e++)
#pragma unroll
        for (int off = 16; off > 0; off >>= 1)
            sums[e] += __shfl_xor_sync(0xFFFFFFFFu, sums[e], off);
    if (lane == 0) {
        int i0 = 0; float v0 = sums[0];
#pragma unroll
        for (int e = 1; e < EE; e++) if (sums[e] > v0) { v0 = sums[e]; i0 = e; }
        int i1 = -1; float v1 = -1e30f;
#pragma unroll
        for (int e = 0; e < EE; e++) {
            if (e == i0) continue;
            if (sums[e] > v1) { v1 = sums[e]; i1 = e; }
        }
        float e1 = expf(v1 - v0);
        float inv = 1.0f / (1.0f + e1);
        g_eidx[2 * w + 0] = i0;  g_eidx[2 * w + 1] = i1;
        g_ew[2 * w + 0] = inv;   g_ew[2 * w + 1] = e1 * inv;
    }
}

// ---------------- Kernel 3: GEMM1  h = tf32(w * gelu(x @ W1 + b1)) ----------
// g_h written k-permuted within 8-groups via lane-pair shuffle + float4 stores.
__global__ __launch_bounds__(NTH, 1)
void moe_gemm1(const float* __restrict__ b1p) {
    extern __shared__ uint32_t smu[];
    int slot = blockIdx.z, b = slot >> 1;
    int e = g_eidx[slot];
    float wgt = g_ew[slot];
    int tile_m = blockIdx.y * BM, tile_n = blockIdx.x * BN;

    const float* A  = g_xr  + (size_t)b * TT * DD + (size_t)tile_m * DD;
    const float* Bp = g_w1r + (size_t)e * DD * FF + tile_n;

    float acc[2][8][4];
#pragma unroll
    for (int i = 0; i < 2; i++)
#pragma unroll
        for (int j = 0; j < 8; j++)
#pragma unroll
            for (int q = 0; q < 4; q++) acc[i][j][q] = 0.0f;

    gemm_core(A, A, DD, Bp, Bp, FF, DD / BKT, DD / BKT, smu, acc);

    int lane = threadIdx.x & 31, wid = threadIdx.x >> 5;
    int wm = wid & 3, wn = wid >> 2;
    int g = lane >> 2, tig = lane & 3;
    const float* bp = b1p + (size_t)e * FF + tile_n;
    float* C = g_h + ((size_t)slot * TT + tile_m) * FF + tile_n;
#pragma unroll
    for (int mi = 0; mi < 2; mi++) {
#pragma unroll
        for (int h2 = 0; h2 < 2; h2++) {
            int row = wm * 32 + mi * 16 + g + h2 * 8;
            float* Crow = C + (size_t)row * FF;
#pragma unroll
            for (int ni = 0; ni < 8; ni++) {
                int colb = wn * 64 + ni * 8;
                float v0 = acc[mi][ni][h2 * 2 + 0] + bp[colb + 2 * tig];
                float v1 = acc[mi][ni][h2 * 2 + 1] + bp[colb + 2 * tig + 1];
                float o0 = rtf(wgt * 0.5f * v0 * (1.0f + erff(v0 * 0.70710678118654752f)));
                float o1 = rtf(wgt * 0.5f * v1 * (1.0f + erff(v1 * 0.70710678118654752f)));
                // pair lanes tig <-> tig+2: logical k j with k j+4
                float p0 = __shfl_xor_sync(0xFFFFFFFFu, o0, 2);
                float p1 = __shfl_xor_sync(0xFFFFFFFFu, o1, 2);
                if (tig < 2) {
                    float4 q = make_float4(o0, p0, o1, p1);
                    *(float4*)(Crow + colb + 4 * tig) = q;
                }
            }
        }
    }
}

// ---------------- Kernel 4: GEMM2  out = h0@W2[e0] + h1@W2[e1] + wbias ------
__global__ __launch_bounds__(NTH, 1)
void moe_gemm2(const float* __restrict__ b2p, float* __restrict__ out) {
    extern __shared__ uint32_t smu[];
    int b = blockIdx.z;
    int e0 = g_eidx[2 * b], e1 = g_eidx[2 * b + 1];
    float w0 = g_ew[2 * b], w1 = g_ew[2 * b + 1];
    int tile_m = blockIdx.y * BM, tile_n = blockIdx.x * BN;

    const float* A0 = g_h + ((size_t)(2 * b + 0) * TT + tile_m) * FF;
    const float* A1 = g_h + ((size_t)(2 * b + 1) * TT + tile_m) * FF;
    const float* B0 = g_w2r + (size_t)e0 * FF * DD + tile_n;
    const float* B1 = g_w2r + (size_t)e1 * FF * DD + tile_n;

    float acc[2][8][4];
#pragma unroll
    for (int i = 0; i < 2; i++)
#pragma unroll
        for (int j = 0; j < 8; j++)
#pragma unroll
            for (int q = 0; q < 4; q++) acc[i][j][q] = 0.0f;

    gemm_core(A0, A1, FF, B0, B1, DD, 2 * FF / BKT, FF / BKT, smu, acc);

    int lane = threadIdx.x & 31, wid = threadIdx.x >> 5;
    int wm = wid & 3, wn = wid >> 2;
    int g = lane >> 2, tig = lane & 3;
    const float* bp0 = b2p + (size_t)e0 * DD + tile_n;
    const float* bp1 = b2p + (size_t)e1 * DD + tile_n;
    float* C = out + ((size_t)b * TT + tile_m) * DD + tile_n;
#pragma unroll
    for (int mi = 0; mi < 2; mi++) {
#pragma unroll
        for (int h2 = 0; h2 < 2; h2++) {
            int row = wm * 32 + mi * 16 + g + h2 * 8;
            float* Crow = C + (size_t)row * DD;
#pragma unroll
            for (int ni = 0; ni < 8; ni++) {
                int col = wn * 64 + ni * 8 + 2 * tig;
                float2 o;
                o.x = acc[mi][ni][h2 * 2 + 0] + w0 * bp0[col]     + w1 * bp1[col];
                o.y = acc[mi][ni][h2 * 2 + 1] + w0 * bp0[col + 1] + w1 * bp1[col + 1];
                *(float2*)(Crow + col) = o;
            }
        }
    }
}

// ---------------------------------------------------------------------------
extern "C" void kernel_launch(void* const* d_in, const int* in_sizes, int n_in,
                              void* d_out, int out_size) {
    const float* x  = (const float*)d_in[0];
    const float* Wr = (const float*)d_in[1];
    const float* W1 = (const float*)d_in[2];
    const float* b1 = (const float*)d_in[3];
    const float* W2 = (const float*)d_in[4];
    const float* b2 = (const float*)d_in[5];
    float* out = (float*)d_out;

    static int inited = 0;
    if (!inited) {
        cudaFuncSetAttribute(moe_gemm1, cudaFuncAttributeMaxDynamicSharedMemorySize, SMEM_BYTES);
        cudaFuncSetAttribute(moe_gemm2, cudaFuncAttributeMaxDynamicSharedMemorySize, SMEM_BYTES);
        inited = 1;
    }

    float* w1r; cudaGetSymbolAddress((void**)&w1r, g_w1r);
    float* w2r; cudaGetSymbolAddress((void**)&w2r, g_w2r);

    prep_x<<<(BB * TT * DD / 8) / 256, 256>>>(x);
    prep_w<<<((size_t)EE * DD * FF / 32) / 256, 256>>>(W1, w1r);
    prep_w<<<((size_t)EE * FF * DD / 32) / 256, 256>>>(W2, w2r);
    pool_kernel<<<dim3(BB, DD / 256, 8), 256>>>(x);
    route_kernel<<<1, 256>>>(Wr);
    moe_gemm1<<<dim3(FF / BN, TT / BM, BB * 2), NTH, SMEM_BYTES>>>(b1);
    moe_gemm2<<<dim3(DD / BN, TT / BM, BB), NTH, SMEM_BYTES>>>(b2, out);
}

// round 15
// speedup vs baseline: 1.1347x; 1.1347x over previous
#include <cuda_runtime.h>
#include <math.h>
#include <stdint.h>

#define BB 8
#define TT 2048
#define DD 1024
#define FF 4096
#define EE 8

#define BM 128
#define BN 256
#define BKT 32
#define NTH 512
#define LDAU 32          // A smem row stride (u32): 128B rows, chunk-XOR swizzle
#define LDBU 264         // B smem row stride (u32) = 66 16B chunks

#define ASTG (BM * LDAU)     // 4096 u32 = 16KB
#define BSTG (BKT * LDBU)    // 8448 u32 = 33792B
#define STGU (ASTG + BSTG)   // u32 per stage
#define NSTAGE 4
#define SMEM_BYTES (NSTAGE * STGU * 4)   // 200704 B

// ---------------- device scratch (no allocation allowed) -------------------
__device__ float g_pp[8 * BB * DD];               // pool partials (8 T-chunks)
__device__ int   g_eidx[BB * 2];
__device__ float g_ew[BB * 2];
__device__ float g_xr[(size_t)BB * TT * DD];      // 64MB: tf32-rounded x
__device__ float g_w1r[(size_t)EE * DD * FF];     // 128MB: tf32 W1, col-perm in 32-groups
__device__ float g_w2r[(size_t)EE * FF * DD];     // 128MB: tf32 W2, col-perm in 32-groups
__device__ float g_h[(size_t)BB * 2 * TT * FF];   // 512MB: tf32(w*gelu(x@W1+b1))

// ---------------- helpers ---------------------------------------------------
static __device__ __forceinline__ uint32_t smem_u32(const void* p) {
    uint32_t a;
    asm("{ .reg .u64 t; cvta.to.shared.u64 t, %1; cvt.u32.u64 %0, t; }" : "=r"(a) : "l"(p));
    return a;
}
static __device__ __forceinline__ uint32_t f2tf(float f) {
    uint32_t r;
    asm("cvt.rna.tf32.f32 %0, %1;" : "=r"(r) : "f"(f));
    return r;
}
static __device__ __forceinline__ float rtf(float f) { return __uint_as_float(f2tf(f)); }
static __device__ __forceinline__ void mma8(float* c, const uint32_t* a, const uint32_t* b) {
    asm volatile(
        "mma.sync.aligned.m16n8k8.row.col.f32.tf32.tf32.f32 "
        "{%0,%1,%2,%3}, {%4,%5,%6,%7}, {%8,%9}, {%0,%1,%2,%3};"
        : "+f"(c[0]), "+f"(c[1]), "+f"(c[2]), "+f"(c[3])
        : "r"(a[0]), "r"(a[1]), "r"(a[2]), "r"(a[3]), "r"(b[0]), "r"(b[1]));
}
static __device__ __forceinline__ void cpa16(uint32_t dst, const float* src) {
    asm volatile("cp.async.cg.shared.global [%0], [%1], 16;" :: "r"(dst), "l"(src));
}
static __device__ __forceinline__ void cpa_commit() {
    asm volatile("cp.async.commit_group;" ::: "memory");
}
static __device__ __forceinline__ void cpa_wait0() {
    asm volatile("cp.async.wait_group 0;" ::: "memory");
}
static __device__ __forceinline__ void cpa_wait1() {
    asm volatile("cp.async.wait_group 1;" ::: "memory");
}
static __device__ __forceinline__ void cpa_wait2() {
    asm volatile("cp.async.wait_group 2;" ::: "memory");
}

// Issue one full stage (A tile + B tile) as one cp.async commit group.
// A: 128 rows x 32 k, 16B chunks XOR-swizzled by row&7.
// B: 32 k x 256 n (pre-permuted in gmem), rows padded to 66 chunks.
static __device__ __forceinline__ void issue_stage(
    uint32_t base, const float* __restrict__ A, int lda,
    const float* __restrict__ B, int ldb, int tid)
{
#pragma unroll
    for (int it = 0; it < 2; it++) {
        int r = (tid >> 3) + it * 64;
        int c = tid & 7;
        cpa16(base + (uint32_t)(r * LDAU + ((c ^ (r & 7)) << 2)) * 4u,
              A + (size_t)r * lda + c * 4);
    }
#pragma unroll
    for (int it = 0; it < 4; it++) {
        int idx = it * NTH + tid;
        int k = idx >> 6, c = idx & 63;
        cpa16(base + (uint32_t)ASTG * 4u + (uint32_t)(k * 66 + c) * 16u,
              B + (size_t)k * ldb + c * 4);
    }
    cpa_commit();
}

// Compute 32-k block. Warp grid 4m x 4n: warp tile 32(M) x 64(N).
// A frags LDS.32 (swizzled), B frags LDS.128 via n-permuted layout.
static __device__ __forceinline__ void compute32(const uint32_t* __restrict__ as,
                                                 const uint32_t* __restrict__ bs,
                                                 float acc[2][8][4],
                                                 int wm, int wn, int g, int tig) {
#pragma unroll
    for (int ks = 0; ks < 4; ks++) {
        uint32_t a[2][4];
        int c0 = (((2 * ks) ^ g) << 2) + tig;
        int c1 = (((2 * ks + 1) ^ g) << 2) + tig;
#pragma unroll
        for (int mi = 0; mi < 2; mi++) {
            int r0 = (wm * 32 + mi * 16 + g) * LDAU;
            a[mi][0] = as[r0 + c0];
            a[mi][2] = as[r0 + c1];
            a[mi][1] = as[r0 + 8 * LDAU + c0];
            a[mi][3] = as[r0 + 8 * LDAU + c1];
        }
#pragma unroll
        for (int nj = 0; nj < 2; nj++) {
            int nb = wn * 64 + nj * 32 + g * 4;
            uint4 q0 = *(const uint4*)&bs[(ks * 8 + tig) * LDBU + nb];
            uint4 q1 = *(const uint4*)&bs[(ks * 8 + tig + 4) * LDBU + nb];
            uint32_t b0[4] = { q0.x, q0.y, q0.z, q0.w };
            uint32_t b1[4] = { q1.x, q1.y, q1.z, q1.w };
#pragma unroll
            for (int ni = 0; ni < 4; ni++) {
                uint32_t bb[2] = { b0[ni], b1[ni] };
#pragma unroll
                for (int mi = 0; mi < 2; mi++) mma8(acc[mi][nj * 4 + ni], a[mi], bb);
            }
        }
    }
}

// Mainloop: acc(128x256) += [A0;A1] @ [B0;B1]. 4-stage cp.async for A+B.
static __device__ __forceinline__ void gemm_core(
    const float* __restrict__ A0, const float* __restrict__ A1, int lda,
    const float* __restrict__ B0, const float* __restrict__ B1, int ldb,
    int nst, int half, uint32_t* smu, float acc[2][8][4])
{
    int tid = threadIdx.x;
    int wid = tid >> 5, lane = tid & 31;
    int wm = wid & 3, wn = wid >> 2;
    int g = lane >> 2, tig = lane & 3;

    uint32_t sb[NSTAGE];
#pragma unroll
    for (int i = 0; i < NSTAGE; i++) sb[i] = smem_u32(smu + i * STGU);

    // prologue: stages 0,1,2 in flight
#pragma unroll
    for (int t = 0; t < 3; t++) {
        int sel = (t >= half);
        int k0 = (t - (sel ? half : 0)) * BKT;
        issue_stage(sb[t], (sel ? A1 : A0) + k0, lda,
                    (sel ? B1 : B0) + (size_t)k0 * ldb, ldb, tid);
    }
    cpa_wait2();          // stage 0 complete
    __syncthreads();

    for (int s = 0; s < nst; s++) {
        int buf = s & 3;
        if (s + 3 < nst) {
            int t = s + 3;
            int sel = (t >= half);
            int k0 = (t - (sel ? half : 0)) * BKT;
            issue_stage(sb[(s + 3) & 3], (sel ? A1 : A0) + k0, lda,
                        (sel ? B1 : B0) + (size_t)k0 * ldb, ldb, tid);
        }
        const uint32_t* as = smu + buf * STGU;
        compute32(as, as + ASTG, acc, wm, wn, g, tig);
        if (s + 1 < nst) {
            if (s + 3 < nst) cpa_wait2();
            else if (s + 2 < nst) cpa_wait1();
            else cpa_wait0();
            __syncthreads();
        }
    }
}

// ---------------- Kernel 0a: tf32 pre-round of x ----------------------------
__global__ void prep_x(const float* __restrict__ x) {
    size_t i = (size_t)blockIdx.x * blockDim.x + threadIdx.x;
    float4 v = ((const float4*)x)[i];
    float4 o;
    o.x = rtf(v.x); o.y = rtf(v.y); o.z = rtf(v.z); o.w = rtf(v.w);
    ((float4*)g_xr)[i] = o;
}
// ---------------- Kernel 0b: weights -> tf32 + col-perm in 32-groups --------
// out position 4*(n&7)+(n>>3) within each 32-group (matches smem B layout).
__global__ void prep_w(const float* __restrict__ w, float* __restrict__ dst) {
    size_t gidx = (size_t)blockIdx.x * blockDim.x + threadIdx.x;
    const float4* s = (const float4*)w + gidx * 8;
    float v[32];
#pragma unroll
    for (int i = 0; i < 8; i++) {
        float4 t = s[i];
        v[4 * i] = t.x; v[4 * i + 1] = t.y; v[4 * i + 2] = t.z; v[4 * i + 3] = t.w;
    }
    float4* d = (float4*)dst + gidx * 8;
#pragma unroll
    for (int m = 0; m < 8; m++)
        d[m] = make_float4(rtf(v[m]), rtf(v[m + 8]), rtf(v[m + 16]), rtf(v[m + 24]));
}

// ---------------- Kernel 1: mean pool partials (8 T-chunks) -----------------
__global__ void pool_kernel(const float* __restrict__ x) {
    int b = blockIdx.x;
    int d = blockIdx.y * blockDim.x + threadIdx.x;
    int c = blockIdx.z;
    const float* xp = x + (size_t)b * TT * DD + (size_t)(c * (TT / 8)) * DD + d;
    float s = 0.0f;
#pragma unroll 8
    for (int t = 0; t < TT / 8; t++) s += xp[(size_t)t * DD];
    g_pp[(c * BB + b) * DD + d] = s;
}

// ---------------- Kernel 2: routing (reduces pool partials) -----------------
__global__ void route_kernel(const float* __restrict__ Wr) {
    int w = threadIdx.x >> 5;
    int lane = threadIdx.x & 31;
    if (w >= BB) return;
    float sums[EE];
#pragma unroll
    for (int e = 0; e < EE; e++) sums[e] = 0.0f;
    for (int d = lane; d < DD; d += 32) {
        float p = 0.0f;
#pragma unroll
        for (int c = 0; c < 8; c++) p += g_pp[(c * BB + w) * DD + d];
        p *= (1.0f / (float)TT);
        const float* wr = Wr + d * EE;
#pragma unroll
        for (int e = 0; e < EE; e++) sums[e] += p * wr[e];
    }
#pragma unroll
    for (int e = 0; e < EE; e++)
#pragma unroll
        for (int off = 16; off > 0; off >>= 1)
            sums[e] += __shfl_xor_sync(0xFFFFFFFFu, sums[e], off);
    if (lane == 0) {
        int i0 = 0; float v0 = sums[0];
#pragma unroll
        for (int e = 1; e < EE; e++) if (sums[e] > v0) { v0 = sums[e]; i0 = e; }
        int i1 = -1; float v1 = -1e30f;
#pragma unroll
        for (int e = 0; e < EE; e++) {
            if (e == i0) continue;
            if (sums[e] > v1) { v1 = sums[e]; i1 = e; }
        }
        float e1 = expf(v1 - v0);
        float inv = 1.0f / (1.0f + e1);
        g_eidx[2 * w + 0] = i0;  g_eidx[2 * w + 1] = i1;
        g_ew[2 * w + 0] = inv;   g_ew[2 * w + 1] = e1 * inv;
    }
}

// ---------------- Kernel 3: GEMM1  h = tf32(w * gelu(x @ W1 + b1)) ----------
__global__ __launch_bounds__(NTH, 1)
void moe_gemm1(const float* __restrict__ b1p) {
    extern __shared__ uint32_t smu[];
    int slot = blockIdx.z, b = slot >> 1;
    int e = g_eidx[slot];
    float wgt = g_ew[slot];
    int tile_m = blockIdx.y * BM, tile_n = blockIdx.x * BN;

    const float* A  = g_xr  + (size_t)b * TT * DD + (size_t)tile_m * DD;
    const float* Bp = g_w1r + (size_t)e * DD * FF + tile_n;

    float acc[2][8][4];
#pragma unroll
    for (int i = 0; i < 2; i++)
#pragma unroll
        for (int j = 0; j < 8; j++)
#pragma unroll
            for (int q = 0; q < 4; q++) acc[i][j][q] = 0.0f;

    gemm_core(A, A, DD, Bp, Bp, FF, DD / BKT, DD / BKT, smu, acc);

    int lane = threadIdx.x & 31, wid = threadIdx.x >> 5;
    int wm = wid & 3, wn = wid >> 2;
    int g = lane >> 2, tig = lane & 3;
    const float* bp = b1p + (size_t)e * FF + tile_n;
    float* C = g_h + ((size_t)slot * TT + tile_m) * FF + tile_n;
#pragma unroll
    for (int mi = 0; mi < 2; mi++) {
#pragma unroll
        for (int h2 = 0; h2 < 2; h2++) {
            int row = wm * 32 + mi * 16 + g + h2 * 8;
            float* Crow = C + (size_t)row * FF;
#pragma unroll
            for (int ni = 0; ni < 8; ni++) {
                int col = wn * 64 + ni * 8 + 2 * tig;
                float v0 = acc[mi][ni][h2 * 2 + 0] + bp[col];
                float v1 = acc[mi][ni][h2 * 2 + 1] + bp[col + 1];
                float2 o;
                o.x = rtf(wgt * 0.5f * v0 * (1.0f + erff(v0 * 0.70710678118654752f)));
                o.y = rtf(wgt * 0.5f * v1 * (1.0f + erff(v1 * 0.70710678118654752f)));
                *(float2*)(Crow + col) = o;
            }
        }
    }
}

// ---------------- Kernel 4: GEMM2  out = h0@W2[e0] + h1@W2[e1] + wbias ------
__global__ __launch_bounds__(NTH, 1)
void moe_gemm2(const float* __restrict__ b2p, float* __restrict__ out) {
    extern __shared__ uint32_t smu[];
    int b = blockIdx.z;
    int e0 = g_eidx[2 * b], e1 = g_eidx[2 * b + 1];
    float w0 = g_ew[2 * b], w1 = g_ew[2 * b + 1];
    int tile_m = blockIdx.y * BM, tile_n = blockIdx.x * BN;

    const float* A0 = g_h + ((size_t)(2 * b + 0) * TT + tile_m) * FF;
    const float* A1 = g_h + ((size_t)(2 * b + 1) * TT + tile_m) * FF;
    const float* B0 = g_w2r + (size_t)e0 * FF * DD + tile_n;
    const float* B1 = g_w2r + (size_t)e1 * FF * DD + tile_n;

    float acc[2][8][4];
#pragma unroll
    for (int i = 0; i < 2; i++)
#pragma unroll
        for (int j = 0; j < 8; j++)
#pragma unroll
            for (int q = 0; q < 4; q++) acc[i][j][q] = 0.0f;

    gemm_core(A0, A1, FF, B0, B1, DD, 2 * FF / BKT, FF / BKT, smu, acc);

    int lane = threadIdx.x & 31, wid = threadIdx.x >> 5;
    int wm = wid & 3, wn = wid >> 2;
    int g = lane >> 2, tig = lane & 3;
    const float* bp0 = b2p + (size_t)e0 * DD + tile_n;
    const float* bp1 = b2p + (size_t)e1 * DD + tile_n;
    float* C = out + ((size_t)b * TT + tile_m) * DD + tile_n;
#pragma unroll
    for (int mi = 0; mi < 2; mi++) {
#pragma unroll
        for (int h2 = 0; h2 < 2; h2++) {
            int row = wm * 32 + mi * 16 + g + h2 * 8;
            float* Crow = C + (size_t)row * DD;
#pragma unroll
            for (int ni = 0; ni < 8; ni++) {
                int col = wn * 64 + ni * 8 + 2 * tig;
                float2 o;
                o.x = acc[mi][ni][h2 * 2 + 0] + w0 * bp0[col]     + w1 * bp1[col];
                o.y = acc[mi][ni][h2 * 2 + 1] + w0 * bp0[col + 1] + w1 * bp1[col + 1];
                *(float2*)(Crow + col) = o;
            }
        }
    }
}

// ---------------------------------------------------------------------------
extern "C" void kernel_launch(void* const* d_in, const int* in_sizes, int n_in,
                              void* d_out, int out_size) {
    const float* x  = (const float*)d_in[0];
    const float* Wr = (const float*)d_in[1];
    const float* W1 = (const float*)d_in[2];
    const float* b1 = (const float*)d_in[3];
    const float* W2 = (const float*)d_in[4];
    const float* b2 = (const float*)d_in[5];
    float* out = (float*)d_out;

    static int inited = 0;
    if (!inited) {
        cudaFuncSetAttribute(moe_gemm1, cudaFuncAttributeMaxDynamicSharedMemorySize, SMEM_BYTES);
        cudaFuncSetAttribute(moe_gemm2, cudaFuncAttributeMaxDynamicSharedMemorySize, SMEM_BYTES);
        inited = 1;
    }

    float* w1r; cudaGetSymbolAddress((void**)&w1r, g_w1r);
    float* w2r; cudaGetSymbolAddress((void**)&w2r, g_w2r);

    prep_x<<<(BB * TT * DD / 4) / 256, 256>>>(x);
    prep_w<<<((size_t)EE * DD * FF / 32) / 256, 256>>>(W1, w1r);
    prep_w<<<((size_t)EE * FF * DD / 32) / 256, 256>>>(W2, w2r);
    pool_kernel<<<dim3(BB, DD / 256, 8), 256>>>(x);
    route_kernel<<<1, 256>>>(Wr);
    moe_gemm1<<<dim3(FF / BN, TT / BM, BB * 2), NTH, SMEM_BYTES>>>(b1);
    moe_gemm2<<<dim3(DD / BN, TT / BM, BB), NTH, SMEM_BYTES>>>(b2, out);
}